// round 12
// baseline (speedup 1.0000x reference)
#include <cuda_runtime.h>
#include <cuda_fp16.h>
#include <math.h>
#include <stdint.h>

// Problem constants
#define B_    8
#define S_    512
#define H_    4096
#define HQ_   32
#define HKV_  8
#define D_    128
#define L_    1536
#define T_    2048
#define NT_   (B_*S_)
#define THETA_ 500000.0f
#define NQKV  (H_ + 2*HKV_*D_)      // 6144
// -log2(THETA)/64
#define ROPE_C (-0.2958058953f)

// ---------------- scratch (device globals) ----------------------------------
__device__ __half g_hid_h [(size_t)NT_*H_];
__device__ __half g_wqkvT_h[(size_t)NQKV*H_];
__device__ __half g_woT_h [(size_t)H_*H_];
__device__ __half g_attb_h[(size_t)NT_*H_];

__device__ __half g_qb_h[(size_t)NT_*HQ_*D_];
__device__ __half g_qb_l[(size_t)NT_*HQ_*D_];
__device__ __half g_kb_h[(size_t)B_*T_*HKV_*D_];
__device__ __half g_vb_h[(size_t)B_*T_*HKV_*D_];

// ---------------- helpers ----------------------------------------------------
__device__ __forceinline__ uint32_t smem_u32(const void* p) {
    uint32_t r;
    asm("{ .reg .u64 t; cvta.to.shared.u64 t, %1; cvt.u32.u64 %0, t; }"
        : "=r"(r) : "l"(p));
    return r;
}
__device__ __forceinline__ uint16_t h_hi(float x) {
    __half h = __float2half_rn(x);
    return *reinterpret_cast<uint16_t*>(&h);
}
__device__ __forceinline__ float h_back(uint16_t u) {
    __half h = *reinterpret_cast<__half*>(&u);
    return __half2float(h);
}
__device__ __forceinline__ uint32_t pack_h2(float lo, float hi) {
    __half2 h = __floats2half2_rn(lo, hi);       // lo -> low half
    return *reinterpret_cast<uint32_t*>(&h);
}

#define CP_ASYNC16(dst, src) \
    asm volatile("cp.async.cg.shared.global [%0], [%1], 16;" :: "r"(dst), "l"(src))
#define CP_COMMIT() asm volatile("cp.async.commit_group;")
#define CP_WAIT2()  asm volatile("cp.async.wait_group 2;")
#define CP_WAIT1()  asm volatile("cp.async.wait_group 1;")
#define CP_WAIT0()  asm volatile("cp.async.wait_group 0;")

#define LDSM4(r, a) \
    asm volatile("ldmatrix.sync.aligned.m8n8.x4.shared.b16 {%0,%1,%2,%3}, [%4];" \
                 : "=r"((r)[0]), "=r"((r)[1]), "=r"((r)[2]), "=r"((r)[3]) : "r"(a))
#define LDSM4T(r, a) \
    asm volatile("ldmatrix.sync.aligned.m8n8.x4.trans.shared.b16 {%0,%1,%2,%3}, [%4];" \
                 : "=r"((r)[0]), "=r"((r)[1]), "=r"((r)[2]), "=r"((r)[3]) : "r"(a))

#define MMA_F16(c, a, b0v, b1v) \
    asm volatile("mma.sync.aligned.m16n8k16.row.col.f32.f16.f16.f32 " \
                 "{%0,%1,%2,%3}, {%4,%5,%6,%7}, {%8,%9}, {%0,%1,%2,%3};" \
                 : "+f"((c)[0]), "+f"((c)[1]), "+f"((c)[2]), "+f"((c)[3]) \
                 : "r"((a)[0]), "r"((a)[1]), "r"((a)[2]), "r"((a)[3]), \
                   "r"(b0v), "r"(b1v))

// ---------------- fp32 -> fp16 (hi only) -------------------------------------
__global__ void conv_h(const float4* __restrict__ in, uint2* __restrict__ oh, int n4)
{
    int i = blockIdx.x * blockDim.x + threadIdx.x;
    if (i >= n4) return;
    float4 v = in[i];
    oh[i] = make_uint2(pack_h2(v.x, v.y), pack_h2(v.z, v.w));
}

// ---------------- fp32 [K][N] -> fp16 transposed [N][K] ----------------------
// perm != 0: head-local row permutation d -> (d<64 ? 2d : 2(d-64)+1)
__global__ void conv_hT(const float* __restrict__ in,
                        __half* __restrict__ oh, int K, int N, int perm)
{
    __shared__ float t[64][33];
    const int n0 = blockIdx.x * 32;
    const int k0 = blockIdx.y * 64;
    const int x = threadIdx.x & 31;
    const int y = threadIdx.x >> 5;        // 0..7
#pragma unroll
    for (int it = 0; it < 8; it++) {
        int row = it * 8 + y;
        t[row][x] = in[(size_t)(k0 + row) * N + n0 + x];
    }
    __syncthreads();
    const int u  = threadIdx.x & 31;       // k-pair index
    const int nr = threadIdx.x >> 5;       // 0..7
    uint16_t* o16 = reinterpret_cast<uint16_t*>(oh);
#pragma unroll
    for (int it = 0; it < 4; it++) {
        int n = it * 8 + nr;
        int gn = n0 + n;
        int dst = gn;
        if (perm) {
            int d = gn & 127;
            int pd = (d < 64) ? (2 * d) : (2 * (d - 64) + 1);
            dst = (gn & ~127) | pd;
        }
        uint32_t p = pack_h2(t[2 * u][n], t[2 * u + 1][n]);
        *reinterpret_cast<uint32_t*>(o16 + (size_t)dst * K + k0 + 2 * u) = p;
    }
}

// ============================================================================
// fp16 1-term GEMM, 2 CTAs/SM. mode 0: fp32 out; mode 1: fused QKV epilogue.
// ============================================================================
#define GSTAGE 16384
#define GEMM_SMEM (3 * GSTAGE)

__global__ __launch_bounds__(256, 2) void gemm_h1(
    const __half* __restrict__ Ah, const __half* __restrict__ Bh,
    float* __restrict__ C0, int ld0, int K, int mode)
{
    extern __shared__ char smem[];
    const uint32_t sb = smem_u32(smem);
    const int tid  = threadIdx.x;
    const int lane = tid & 31;
    const int wid  = tid >> 5;
    const int bm   = blockIdx.y * 128;
    const int bn   = blockIdx.x * 128;
    const int wm   = (wid >> 2) * 64;
    const int wn   = (wid & 3) * 32;

    const int lrow = tid >> 2;
    const int lchk = tid & 3;
    const uint32_t dsw = (uint32_t)(lrow * 64 + ((lchk ^ ((lrow >> 1) & 3)) * 16));

    const int arow = ((lane >> 3) & 1) * 8 + (lane & 7);
    const int akc  = lane >> 4;
    const int aph  = ((lane & 7) >> 1) & 3;
    const uint32_t aBase = (uint32_t)((wm + arow) * 64);

    const int brow8 = lane & 7;
    const int bkc   = (lane >> 3) & 1;
    const int bj1   = (lane >> 4) & 1;
    const int bph   = (brow8 >> 1) & 3;
    const uint32_t bBase = (uint32_t)((wn + bj1 * 8 + brow8) * 64);

    float acc[4][4][4];
#pragma unroll
    for (int i = 0; i < 4; i++)
#pragma unroll
        for (int j = 0; j < 4; j++) {
            acc[i][j][0] = 0.f; acc[i][j][1] = 0.f;
            acc[i][j][2] = 0.f; acc[i][j][3] = 0.f;
        }

    const int nk = K / 32;

    auto issue = [&](int st, int k0) {
        const uint32_t s = sb + st * GSTAGE;
        {
            const __half* g = Ah + (size_t)(bm + lrow) * K + k0 + lchk * 8;
            uint32_t d = s + dsw;
            CP_ASYNC16(d, g);
            CP_ASYNC16(d + 4096, g + (size_t)64 * K);
        }
        {
            const __half* g = Bh + (size_t)(bn + lrow) * K + k0 + lchk * 8;
            uint32_t d = s + 8192 + dsw;
            CP_ASYNC16(d, g);
            CP_ASYNC16(d + 4096, g + (size_t)64 * K);
        }
        CP_COMMIT();
    };

    issue(0, 0);
    issue(1, 32);
    issue(2, 64);

    int st = 0;
    for (int ck = 0; ck < nk; ck++) {
        const int rem = nk - 1 - ck;
        if (rem >= 2) { CP_WAIT2(); } else if (rem == 1) { CP_WAIT1(); } else { CP_WAIT0(); }
        __syncthreads();

        const uint32_t s   = sb + st * GSTAGE;
        const uint32_t sA  = s + aBase;
        const uint32_t sBH = s + 8192 + bBase;

#pragma unroll
        for (int ks = 0; ks < 2; ks++) {
            const uint32_t cA = (uint32_t)(((ks * 2 + akc) ^ aph) * 16);
            const uint32_t cB = (uint32_t)(((ks * 2 + bkc) ^ bph) * 16);

            uint32_t aF[4][4];
#pragma unroll
            for (int i = 0; i < 4; i++) LDSM4(aF[i], sA + i * 1024 + cA);

            uint32_t bH[4][2];
#pragma unroll
            for (int jp = 0; jp < 2; jp++) {
                uint32_t r4[4];
                LDSM4(r4, sBH + jp * 1024 + cB);
                bH[2*jp][0] = r4[0]; bH[2*jp][1] = r4[1];
                bH[2*jp+1][0] = r4[2]; bH[2*jp+1][1] = r4[3];
            }

#pragma unroll
            for (int i = 0; i < 4; i++)
#pragma unroll
                for (int j = 0; j < 4; j++)
                    MMA_F16(acc[i][j], aF[i], bH[j][0], bH[j][1]);
        }
        __syncthreads();
        if (ck + 3 < nk) issue(st, (ck + 3) * 32);
        st = (st == 2) ? 0 : st + 1;
    }

    const int g4 = lane >> 2, t4 = lane & 3;

    if (mode == 0) {
        // plain fp32 output
#pragma unroll
        for (int i = 0; i < 4; i++) {
            const int row = bm + wm + i * 16 + g4;
#pragma unroll
            for (int j = 0; j < 4; j++) {
                const int col = bn + wn + j * 8 + t4 * 2;
                *reinterpret_cast<float2*>(&C0[(size_t)row * ld0 + col]) =
                    make_float2(acc[i][j][0], acc[i][j][1]);
                *reinterpret_cast<float2*>(&C0[(size_t)(row + 8) * ld0 + col]) =
                    make_float2(acc[i][j][2], acc[i][j][3]);
            }
        }
        return;
    }

    // ---- fused QKV epilogue ----
    uint16_t* qh16 = reinterpret_cast<uint16_t*>(g_qb_h);
    uint16_t* ql16 = reinterpret_cast<uint16_t*>(g_qb_l);
    uint16_t* kh16 = reinterpret_cast<uint16_t*>(g_kb_h);
    uint16_t* vh16 = reinterpret_cast<uint16_t*>(g_vb_h);

    if (bn < H_) {
        // Q: RoPE pair in adjacent cols; write hi+lo
#pragma unroll
        for (int j = 0; j < 4; j++) {
            const int c = bn + wn + j * 8 + t4 * 2;
            const int head = c >> 7;
            const int f = (c & 127) >> 1;
            const float invf = exp2f((float)f * ROPE_C);
#pragma unroll
            for (int i = 0; i < 4; i++) {
                const int r0 = bm + wm + i * 16 + g4;
#pragma unroll
                for (int hrow = 0; hrow < 2; hrow++) {
                    const int r = r0 + hrow * 8;
                    const float x1 = acc[i][j][hrow * 2];
                    const float x2 = acc[i][j][hrow * 2 + 1];
                    float ang = (float)(L_ + (r & 511)) * invf;
                    float cth, sth;
                    sincosf(ang, &sth, &cth);
                    float y1 = x1 * cth - x2 * sth;
                    float y2 = x2 * cth + x1 * sth;
                    size_t base = (size_t)r * (HQ_ * D_) + head * D_ + f;
                    uint16_t h1 = h_hi(y1), h2 = h_hi(y2);
                    qh16[base]      = h1;
                    qh16[base + 64] = h2;
                    ql16[base]      = h_hi(y1 - h_back(h1));
                    ql16[base + 64] = h_hi(y2 - h_back(h2));
                }
            }
        }
    } else if (bn < H_ + HKV_ * D_) {
        // K: RoPE + scatter to cache layout (hi only)
#pragma unroll
        for (int j = 0; j < 4; j++) {
            const int c = bn + wn + j * 8 + t4 * 2 - H_;
            const int kvh = c >> 7;
            const int f = (c & 127) >> 1;
            const float invf = exp2f((float)f * ROPE_C);
#pragma unroll
            for (int i = 0; i < 4; i++) {
                const int r0 = bm + wm + i * 16 + g4;
#pragma unroll
                for (int hrow = 0; hrow < 2; hrow++) {
                    const int r = r0 + hrow * 8;
                    const int bb = r >> 9;
                    const int ss = r & 511;
                    const float x1 = acc[i][j][hrow * 2];
                    const float x2 = acc[i][j][hrow * 2 + 1];
                    float ang = (float)(L_ + ss) * invf;
                    float cth, sth;
                    sincosf(ang, &sth, &cth);
                    float y1 = x1 * cth - x2 * sth;
                    float y2 = x2 * cth + x1 * sth;
                    size_t o = (((size_t)(bb * T_ + L_ + ss)) * HKV_ + kvh) * D_ + f;
                    kh16[o]      = h_hi(y1);
                    kh16[o + 64] = h_hi(y2);
                }
            }
        }
    } else {
        // V: plain fp16 scatter to cache layout
#pragma unroll
        for (int j = 0; j < 4; j++) {
            const int c = bn + wn + j * 8 + t4 * 2 - (H_ + HKV_ * D_);
            const int kvh = c >> 7;
            const int d = c & 127;
#pragma unroll
            for (int i = 0; i < 4; i++) {
                const int r0 = bm + wm + i * 16 + g4;
#pragma unroll
                for (int hrow = 0; hrow < 2; hrow++) {
                    const int r = r0 + hrow * 8;
                    const int bb = r >> 9;
                    const int ss = r & 511;
                    size_t o = (((size_t)(bb * T_ + L_ + ss)) * HKV_ + kvh) * D_ + d;
                    *reinterpret_cast<uint32_t*>(vh16 + o) =
                        pack_h2(acc[i][j][hrow * 2], acc[i][j][hrow * 2 + 1]);
                }
            }
        }
    }
}

// ---------------- cache -> fp16 (hi only) ------------------------------------
__global__ void copy_cache_kernel(const float4* __restrict__ kc,
                                  const float4* __restrict__ vc)
{
    int idx = blockIdx.x * blockDim.x + threadIdx.x;
    const int n = B_ * L_ * HKV_ * D_ / 4;
    if (idx >= n) return;
    const int perb4 = L_ * HKV_ * D_ / 4;
    int b = idx / perb4;
    size_t o = ((size_t)idx + (size_t)b * ((T_ - L_) * HKV_ * D_ / 4)) * 4;
    float4 k = kc[idx];
    float4 v = vc[idx];
    *reinterpret_cast<uint2*>(reinterpret_cast<uint16_t*>(g_kb_h) + o) =
        make_uint2(pack_h2(k.x, k.y), pack_h2(k.z, k.w));
    *reinterpret_cast<uint2*>(reinterpret_cast<uint16_t*>(g_vb_h) + o) =
        make_uint2(pack_h2(v.x, v.y), pack_h2(v.z, v.w));
}

// ============================================================================
// Tensor-core flash attention: QK 2-term (Qh+Ql vs Kh), PV 1-term (unchanged)
// ============================================================================
#define AT_STAGE 32768
#define AT_SMEM  (2 * AT_STAGE)
#define SC_LOG2E 0.12751884817f

__global__ __launch_bounds__(256, 1) void attn_mma()
{
    extern __shared__ char smem[];
    const uint32_t sb = smem_u32(smem);
    const int tid  = threadIdx.x;
    const int lane = tid & 31;
    const int w    = tid >> 5;
    const int g    = lane >> 2;
    const int t4   = lane & 3;
    const int qt   = blockIdx.x;
    const int hq   = blockIdx.y;
    const int b    = blockIdx.z;
    const int kvh  = hq >> 2;

    {
        const int qr  = tid >> 1;
        const int qcb = (tid & 1) * 8;
        const size_t qo = ((size_t)(b * S_ + qt * 128 + qr)) * (HQ_ * D_) + hq * D_;
#pragma unroll
        for (int i = 0; i < 8; i++) {
            int ch = qcb + i;
            uint32_t d = sb + qr * 256 + ((ch ^ (qr & 7)) * 16);
            CP_ASYNC16(d,         g_qb_h + qo + ch * 8);
            CP_ASYNC16(d + 32768, g_qb_l + qo + ch * 8);
        }
        CP_COMMIT();
        CP_WAIT0();
    }
    __syncthreads();

    uint32_t qh[8][4], ql[8][4];
    {
        const int tt  = lane >> 3;
        const int qrow = 16 * w + (tt & 1) * 8 + (lane & 7);
        const int chi  = tt >> 1;
#pragma unroll
        for (int kk = 0; kk < 8; kk++) {
            uint32_t a = sb + qrow * 256 + (((2 * kk + chi) ^ (qrow & 7)) * 16);
            LDSM4(qh[kk], a);
            LDSM4(ql[kk], a + 32768);
        }
    }
    __syncthreads();

    const int ntiles = 26 + 2 * qt;
    const int mask_from = 24 + 2 * qt;

    auto issueKV = [&](int stage, int kt) {
        const uint32_t s = sb + stage * AT_STAGE;
        const int trow = tid >> 2;
        const int cb   = (tid & 3) * 4;
        const size_t go = (((size_t)(b * T_ + kt * 64 + trow)) * HKV_ + kvh) * D_;
        const uint32_t rb = s + trow * 256;
#pragma unroll
        for (int i = 0; i < 4; i++) {
            int ch = cb + i;
            uint32_t d = rb + ((ch ^ (trow & 7)) * 16);
            CP_ASYNC16(d,         g_kb_h + go + ch * 8);
            CP_ASYNC16(d + 16384, g_vb_h + go + ch * 8);
        }
        CP_COMMIT();
    };

    issueKV(0, 0);
    issueKV(1, 1);

    float oacc[16][4];
#pragma unroll
    for (int j = 0; j < 16; j++) {
        oacc[j][0] = 0.f; oacc[j][1] = 0.f; oacc[j][2] = 0.f; oacc[j][3] = 0.f;
    }
    float m0 = -1e30f, m1 = -1e30f, l0 = 0.f, l1 = 0.f;

    const int tt   = lane >> 3;
    const int krb  = (tt >> 1) * 8 + (lane & 7);
    const int kch1 = tt & 1;
    const int vrb  = (tt & 1) * 8 + (lane & 7);
    const int vch1 = tt >> 1;

    for (int kt = 0; kt < ntiles; kt++) {
        if (kt + 1 < ntiles) { CP_WAIT1(); } else { CP_WAIT0(); }
        __syncthreads();

        const uint32_t s = sb + (kt & 1) * AT_STAGE;

        float sacc[8][4];
#pragma unroll
        for (int j = 0; j < 8; j++) {
            sacc[j][0] = 0.f; sacc[j][1] = 0.f; sacc[j][2] = 0.f; sacc[j][3] = 0.f;
        }
#pragma unroll
        for (int kk = 0; kk < 8; kk++) {
#pragma unroll
            for (int jp = 0; jp < 4; jp++) {
                const int trow = jp * 16 + krb;
                const uint32_t addr = s + trow * 256 +
                                      (((2 * kk + kch1) ^ (trow & 7)) * 16);
                uint32_t bh[4];
                LDSM4(bh, addr);
                MMA_F16(sacc[2*jp],   qh[kk], bh[0], bh[1]);
                MMA_F16(sacc[2*jp+1], qh[kk], bh[2], bh[3]);
                MMA_F16(sacc[2*jp],   ql[kk], bh[0], bh[1]);
                MMA_F16(sacc[2*jp+1], ql[kk], bh[2], bh[3]);
            }
        }

        if (kt >= mask_from) {
            const int colb = kt * 64 + 2 * t4;
            const int alw0 = L_ + qt * 128 + 16 * w + g;
            const int alw1 = alw0 + 8;
#pragma unroll
            for (int j = 0; j < 8; j++) {
                int c0 = colb + j * 8;
                if (c0 > alw0)     sacc[j][0] = -1e30f;
                if (c0 + 1 > alw0) sacc[j][1] = -1e30f;
                if (c0 > alw1)     sacc[j][2] = -1e30f;
                if (c0 + 1 > alw1) sacc[j][3] = -1e30f;
            }
        }

        float rm0 = -1e30f, rm1 = -1e30f;
#pragma unroll
        for (int j = 0; j < 8; j++) {
            rm0 = fmaxf(rm0, fmaxf(sacc[j][0], sacc[j][1]));
            rm1 = fmaxf(rm1, fmaxf(sacc[j][2], sacc[j][3]));
        }
        rm0 = fmaxf(rm0, __shfl_xor_sync(0xFFFFFFFFu, rm0, 1));
        rm0 = fmaxf(rm0, __shfl_xor_sync(0xFFFFFFFFu, rm0, 2));
        rm1 = fmaxf(rm1, __shfl_xor_sync(0xFFFFFFFFu, rm1, 1));
        rm1 = fmaxf(rm1, __shfl_xor_sync(0xFFFFFFFFu, rm1, 2));

        const float nm0 = fmaxf(m0, rm0), nm1 = fmaxf(m1, rm1);
        const float f0 = exp2f((m0 - nm0) * SC_LOG2E);
        const float f1 = exp2f((m1 - nm1) * SC_LOG2E);
        float rs0 = 0.f, rs1 = 0.f;
#pragma unroll
        for (int j = 0; j < 8; j++) {
            sacc[j][0] = exp2f((sacc[j][0] - nm0) * SC_LOG2E);
            sacc[j][1] = exp2f((sacc[j][1] - nm0) * SC_LOG2E);
            sacc[j][2] = exp2f((sacc[j][2] - nm1) * SC_LOG2E);
            sacc[j][3] = exp2f((sacc[j][3] - nm1) * SC_LOG2E);
            rs0 += sacc[j][0] + sacc[j][1];
            rs1 += sacc[j][2] + sacc[j][3];
        }
        rs0 += __shfl_xor_sync(0xFFFFFFFFu, rs0, 1);
        rs0 += __shfl_xor_sync(0xFFFFFFFFu, rs0, 2);
        rs1 += __shfl_xor_sync(0xFFFFFFFFu, rs1, 1);
        rs1 += __shfl_xor_sync(0xFFFFFFFFu, rs1, 2);
        l0 = l0 * f0 + rs0;
        l1 = l1 * f1 + rs1;
        m0 = nm0; m1 = nm1;

#pragma unroll
        for (int j = 0; j < 16; j++) {
            oacc[j][0] *= f0; oacc[j][1] *= f0;
            oacc[j][2] *= f1; oacc[j][3] *= f1;
        }

        uint32_t ph[4][4];
#pragma unroll
        for (int kc = 0; kc < 4; kc++) {
            ph[kc][0] = pack_h2(sacc[2*kc][0],   sacc[2*kc][1]);
            ph[kc][1] = pack_h2(sacc[2*kc][2],   sacc[2*kc][3]);
            ph[kc][2] = pack_h2(sacc[2*kc+1][0], sacc[2*kc+1][1]);
            ph[kc][3] = pack_h2(sacc[2*kc+1][2], sacc[2*kc+1][3]);
        }

        const uint32_t vbase = s + 16384;
#pragma unroll
        for (int jp2 = 0; jp2 < 8; jp2++) {
#pragma unroll
            for (int kc = 0; kc < 4; kc++) {
                const int trow = kc * 16 + vrb;
                const uint32_t addr = vbase + trow * 256 +
                                      (((jp2 * 2 + vch1) ^ (trow & 7)) * 16);
                uint32_t vh[4];
                LDSM4T(vh, addr);
                MMA_F16(oacc[2*jp2],   ph[kc], vh[0], vh[1]);
                MMA_F16(oacc[2*jp2+1], ph[kc], vh[2], vh[3]);
            }
        }

        __syncthreads();
        if (kt + 2 < ntiles) issueKV(kt & 1, kt + 2);
    }

    const float il0 = 1.0f / l0;
    const float il1 = 1.0f / l1;
    const size_t tok0 = (size_t)(b * S_ + qt * 128 + 16 * w + g);
    uint32_t* oh32 = reinterpret_cast<uint32_t*>(g_attb_h);
#pragma unroll
    for (int jn = 0; jn < 16; jn++) {
        float o0 = oacc[jn][0] * il0, o1 = oacc[jn][1] * il0;
        float o2 = oacc[jn][2] * il1, o3 = oacc[jn][3] * il1;
        const size_t a0 = (tok0 * (HQ_ * D_) + hq * D_ + jn * 8 + 2 * t4) >> 1;
        const size_t a1 = a0 + (8 * (HQ_ * D_) >> 1);
        oh32[a0] = pack_h2(o0, o1);
        oh32[a1] = pack_h2(o2, o3);
    }
}

// ---------------- launcher ---------------------------------------------------
extern "C" void kernel_launch(void* const* d_in, const int* in_sizes, int n_in,
                              void* d_out, int out_size)
{
    const float* hidden  = (const float*)d_in[0];
    const float* k_cache = (const float*)d_in[1];
    const float* v_cache = (const float*)d_in[2];
    const float* wq      = (const float*)d_in[3];
    const float* wk      = (const float*)d_in[4];
    const float* wv      = (const float*)d_in[5];
    const float* wo      = (const float*)d_in[6];
    float* out = (float*)d_out;

    __half *hid_h, *wqkv_h, *wo_h, *attb_h;
    cudaGetSymbolAddress((void**)&hid_h,  g_hid_h);
    cudaGetSymbolAddress((void**)&wqkv_h, g_wqkvT_h);
    cudaGetSymbolAddress((void**)&wo_h,   g_woT_h);
    cudaGetSymbolAddress((void**)&attb_h, g_attb_h);

    cudaFuncSetAttribute(gemm_h1,
                         cudaFuncAttributeMaxDynamicSharedMemorySize, GEMM_SMEM);
    cudaFuncSetAttribute(attn_mma,
                         cudaFuncAttributeMaxDynamicSharedMemorySize, AT_SMEM);

    // conversions (Q/K weight sections permuted for fused-RoPE epilogue)
    conv_h<<<(NT_ * H_ / 4 + 255) / 256, 256>>>(
        (const float4*)hidden, (uint2*)hid_h, NT_ * H_ / 4);
    conv_hT<<<dim3(H_ / 32, H_ / 64), 256>>>(wq, wqkv_h, H_, H_, 1);
    conv_hT<<<dim3((HKV_ * D_) / 32, H_ / 64), 256>>>(
        wk, wqkv_h + (size_t)H_ * H_, H_, HKV_ * D_, 1);
    conv_hT<<<dim3((HKV_ * D_) / 32, H_ / 64), 256>>>(
        wv, wqkv_h + (size_t)(H_ + HKV_ * D_) * H_, H_, HKV_ * D_, 0);
    conv_hT<<<dim3(H_ / 32, H_ / 64), 256>>>(wo, wo_h, H_, H_, 0);

    // cache -> fp16
    copy_cache_kernel<<<(B_ * L_ * HKV_ * D_ / 4) / 256, 256>>>(
        (const float4*)k_cache, (const float4*)v_cache);

    // fused QKV projection + RoPE + fp16 split/scatter
    gemm_h1<<<dim3(NQKV / 128, NT_ / 128), 256, GEMM_SMEM>>>(
        hid_h, wqkv_h, out, H_, H_, 1);

    // attention
    attn_mma<<<dim3(S_ / 128, HQ_, B_), 256, AT_SMEM>>>();

    // output projection
    gemm_h1<<<dim3(H_ / 128, NT_ / 128), 256, GEMM_SMEM>>>(
        attb_h, wo_h, out, H_, H_, 0);
}

// round 13
// speedup vs baseline: 1.0903x; 1.0903x over previous
#include <cuda_runtime.h>
#include <cuda_fp16.h>
#include <math.h>
#include <stdint.h>

// Problem constants
#define B_    8
#define S_    512
#define H_    4096
#define HQ_   32
#define HKV_  8
#define D_    128
#define L_    1536
#define T_    2048
#define NT_   (B_*S_)
#define THETA_ 500000.0f
#define NQKV  (H_ + 2*HKV_*D_)      // 6144
// -log2(THETA)/64
#define ROPE_C (-0.2958058953f)

// ---------------- scratch (device globals) ----------------------------------
__device__ __half g_hid_h [(size_t)NT_*H_];
__device__ __half g_wqkvT_h[(size_t)NQKV*H_];
__device__ __half g_woT_h [(size_t)H_*H_];
__device__ __half g_attb_h[(size_t)NT_*H_];

__device__ __half g_qb_h[(size_t)NT_*HQ_*D_];
__device__ __half g_kb_h[(size_t)B_*T_*HKV_*D_];
__device__ __half g_vb_h[(size_t)B_*T_*HKV_*D_];

// ---------------- helpers ----------------------------------------------------
__device__ __forceinline__ uint32_t smem_u32(const void* p) {
    uint32_t r;
    asm("{ .reg .u64 t; cvta.to.shared.u64 t, %1; cvt.u32.u64 %0, t; }"
        : "=r"(r) : "l"(p));
    return r;
}
__device__ __forceinline__ uint16_t h_hi(float x) {
    __half h = __float2half_rn(x);
    return *reinterpret_cast<uint16_t*>(&h);
}
__device__ __forceinline__ uint32_t pack_h2(float lo, float hi) {
    __half2 h = __floats2half2_rn(lo, hi);       // lo -> low half
    return *reinterpret_cast<uint32_t*>(&h);
}

#define CP_ASYNC16(dst, src) \
    asm volatile("cp.async.cg.shared.global [%0], [%1], 16;" :: "r"(dst), "l"(src))
#define CP_COMMIT() asm volatile("cp.async.commit_group;")
#define CP_WAIT2()  asm volatile("cp.async.wait_group 2;")
#define CP_WAIT1()  asm volatile("cp.async.wait_group 1;")
#define CP_WAIT0()  asm volatile("cp.async.wait_group 0;")

#define LDSM4(r, a) \
    asm volatile("ldmatrix.sync.aligned.m8n8.x4.shared.b16 {%0,%1,%2,%3}, [%4];" \
                 : "=r"((r)[0]), "=r"((r)[1]), "=r"((r)[2]), "=r"((r)[3]) : "r"(a))
#define LDSM4T(r, a) \
    asm volatile("ldmatrix.sync.aligned.m8n8.x4.trans.shared.b16 {%0,%1,%2,%3}, [%4];" \
                 : "=r"((r)[0]), "=r"((r)[1]), "=r"((r)[2]), "=r"((r)[3]) : "r"(a))

#define MMA_F16(c, a, b0v, b1v) \
    asm volatile("mma.sync.aligned.m16n8k16.row.col.f32.f16.f16.f32 " \
                 "{%0,%1,%2,%3}, {%4,%5,%6,%7}, {%8,%9}, {%0,%1,%2,%3};" \
                 : "+f"((c)[0]), "+f"((c)[1]), "+f"((c)[2]), "+f"((c)[3]) \
                 : "r"((a)[0]), "r"((a)[1]), "r"((a)[2]), "r"((a)[3]), \
                   "r"(b0v), "r"(b1v))

// ---------------- fp32 -> fp16 (hi only) -------------------------------------
__global__ void conv_h(const float4* __restrict__ in, uint2* __restrict__ oh, int n4)
{
    int i = blockIdx.x * blockDim.x + threadIdx.x;
    if (i >= n4) return;
    float4 v = in[i];
    oh[i] = make_uint2(pack_h2(v.x, v.y), pack_h2(v.z, v.w));
}

// ---------------- fp32 [K][N] -> fp16 transposed [N][K] ----------------------
// perm != 0: head-local row permutation d -> (d<64 ? 2d : 2(d-64)+1)
__global__ void conv_hT(const float* __restrict__ in,
                        __half* __restrict__ oh, int K, int N, int perm)
{
    __shared__ float t[64][33];
    const int n0 = blockIdx.x * 32;
    const int k0 = blockIdx.y * 64;
    const int x = threadIdx.x & 31;
    const int y = threadIdx.x >> 5;        // 0..7
#pragma unroll
    for (int it = 0; it < 8; it++) {
        int row = it * 8 + y;
        t[row][x] = in[(size_t)(k0 + row) * N + n0 + x];
    }
    __syncthreads();
    const int u  = threadIdx.x & 31;       // k-pair index
    const int nr = threadIdx.x >> 5;       // 0..7
    uint16_t* o16 = reinterpret_cast<uint16_t*>(oh);
#pragma unroll
    for (int it = 0; it < 4; it++) {
        int n = it * 8 + nr;
        int gn = n0 + n;
        int dst = gn;
        if (perm) {
            int d = gn & 127;
            int pd = (d < 64) ? (2 * d) : (2 * (d - 64) + 1);
            dst = (gn & ~127) | pd;
        }
        uint32_t p = pack_h2(t[2 * u][n], t[2 * u + 1][n]);
        *reinterpret_cast<uint32_t*>(o16 + (size_t)dst * K + k0 + 2 * u) = p;
    }
}

// ============================================================================
// fp16 1-term GEMM. mode 0: fp32 out; mode 1: fused QKV epilogue (RoPE+scatter)
// ============================================================================
#define GSTAGE 16384
#define GEMM_SMEM (3 * GSTAGE)

__global__ __launch_bounds__(256) void gemm_h1(
    const __half* __restrict__ Ah, const __half* __restrict__ Bh,
    float* __restrict__ C0, int ld0, int K, int mode)
{
    extern __shared__ char smem[];
    const uint32_t sb = smem_u32(smem);
    const int tid  = threadIdx.x;
    const int lane = tid & 31;
    const int wid  = tid >> 5;
    const int bm   = blockIdx.y * 128;
    const int bn   = blockIdx.x * 128;
    const int wm   = (wid >> 2) * 64;
    const int wn   = (wid & 3) * 32;

    const int lrow = tid >> 2;
    const int lchk = tid & 3;
    const uint32_t dsw = (uint32_t)(lrow * 64 + ((lchk ^ ((lrow >> 1) & 3)) * 16));

    const int arow = ((lane >> 3) & 1) * 8 + (lane & 7);
    const int akc  = lane >> 4;
    const int aph  = ((lane & 7) >> 1) & 3;
    const uint32_t aBase = (uint32_t)((wm + arow) * 64);

    const int brow8 = lane & 7;
    const int bkc   = (lane >> 3) & 1;
    const int bj1   = (lane >> 4) & 1;
    const int bph   = (brow8 >> 1) & 3;
    const uint32_t bBase = (uint32_t)((wn + bj1 * 8 + brow8) * 64);

    float acc[4][4][4];
#pragma unroll
    for (int i = 0; i < 4; i++)
#pragma unroll
        for (int j = 0; j < 4; j++) {
            acc[i][j][0] = 0.f; acc[i][j][1] = 0.f;
            acc[i][j][2] = 0.f; acc[i][j][3] = 0.f;
        }

    const int nk = K / 32;

    auto issue = [&](int st, int k0) {
        const uint32_t s = sb + st * GSTAGE;
        {
            const __half* g = Ah + (size_t)(bm + lrow) * K + k0 + lchk * 8;
            uint32_t d = s + dsw;
            CP_ASYNC16(d, g);
            CP_ASYNC16(d + 4096, g + (size_t)64 * K);
        }
        {
            const __half* g = Bh + (size_t)(bn + lrow) * K + k0 + lchk * 8;
            uint32_t d = s + 8192 + dsw;
            CP_ASYNC16(d, g);
            CP_ASYNC16(d + 4096, g + (size_t)64 * K);
        }
        CP_COMMIT();
    };

    issue(0, 0);
    issue(1, 32);
    issue(2, 64);

    int st = 0;
    for (int ck = 0; ck < nk; ck++) {
        const int rem = nk - 1 - ck;
        if (rem >= 2) { CP_WAIT2(); } else if (rem == 1) { CP_WAIT1(); } else { CP_WAIT0(); }
        __syncthreads();

        const uint32_t s   = sb + st * GSTAGE;
        const uint32_t sA  = s + aBase;
        const uint32_t sBH = s + 8192 + bBase;

#pragma unroll
        for (int ks = 0; ks < 2; ks++) {
            const uint32_t cA = (uint32_t)(((ks * 2 + akc) ^ aph) * 16);
            const uint32_t cB = (uint32_t)(((ks * 2 + bkc) ^ bph) * 16);

            uint32_t aF[4][4];
#pragma unroll
            for (int i = 0; i < 4; i++) LDSM4(aF[i], sA + i * 1024 + cA);

            uint32_t bH[4][2];
#pragma unroll
            for (int jp = 0; jp < 2; jp++) {
                uint32_t r4[4];
                LDSM4(r4, sBH + jp * 1024 + cB);
                bH[2*jp][0] = r4[0]; bH[2*jp][1] = r4[1];
                bH[2*jp+1][0] = r4[2]; bH[2*jp+1][1] = r4[3];
            }

#pragma unroll
            for (int i = 0; i < 4; i++)
#pragma unroll
                for (int j = 0; j < 4; j++)
                    MMA_F16(acc[i][j], aF[i], bH[j][0], bH[j][1]);
        }
        __syncthreads();
        if (ck + 3 < nk) issue(st, (ck + 3) * 32);
        st = (st == 2) ? 0 : st + 1;
    }

    const int g4 = lane >> 2, t4 = lane & 3;

    if (mode == 0) {
#pragma unroll
        for (int i = 0; i < 4; i++) {
            const int row = bm + wm + i * 16 + g4;
#pragma unroll
            for (int j = 0; j < 4; j++) {
                const int col = bn + wn + j * 8 + t4 * 2;
                *reinterpret_cast<float2*>(&C0[(size_t)row * ld0 + col]) =
                    make_float2(acc[i][j][0], acc[i][j][1]);
                *reinterpret_cast<float2*>(&C0[(size_t)(row + 8) * ld0 + col]) =
                    make_float2(acc[i][j][2], acc[i][j][3]);
            }
        }
        return;
    }

    // ---- fused QKV epilogue ----
    uint16_t* qh16 = reinterpret_cast<uint16_t*>(g_qb_h);
    uint16_t* kh16 = reinterpret_cast<uint16_t*>(g_kb_h);
    uint16_t* vh16 = reinterpret_cast<uint16_t*>(g_vb_h);

    if (bn < H_) {
        // Q: RoPE pair in adjacent cols (hi only)
#pragma unroll
        for (int j = 0; j < 4; j++) {
            const int c = bn + wn + j * 8 + t4 * 2;
            const int head = c >> 7;
            const int f = (c & 127) >> 1;
            const float invf = exp2f((float)f * ROPE_C);
#pragma unroll
            for (int i = 0; i < 4; i++) {
                const int r0 = bm + wm + i * 16 + g4;
#pragma unroll
                for (int hrow = 0; hrow < 2; hrow++) {
                    const int r = r0 + hrow * 8;
                    const float x1 = acc[i][j][hrow * 2];
                    const float x2 = acc[i][j][hrow * 2 + 1];
                    float ang = (float)(L_ + (r & 511)) * invf;
                    float cth, sth;
                    sincosf(ang, &sth, &cth);
                    float y1 = x1 * cth - x2 * sth;
                    float y2 = x2 * cth + x1 * sth;
                    size_t base = (size_t)r * (HQ_ * D_) + head * D_ + f;
                    qh16[base]      = h_hi(y1);
                    qh16[base + 64] = h_hi(y2);
                }
            }
        }
    } else if (bn < H_ + HKV_ * D_) {
        // K: RoPE + scatter to cache layout (hi only)
#pragma unroll
        for (int j = 0; j < 4; j++) {
            const int c = bn + wn + j * 8 + t4 * 2 - H_;
            const int kvh = c >> 7;
            const int f = (c & 127) >> 1;
            const float invf = exp2f((float)f * ROPE_C);
#pragma unroll
            for (int i = 0; i < 4; i++) {
                const int r0 = bm + wm + i * 16 + g4;
#pragma unroll
                for (int hrow = 0; hrow < 2; hrow++) {
                    const int r = r0 + hrow * 8;
                    const int bb = r >> 9;
                    const int ss = r & 511;
                    const float x1 = acc[i][j][hrow * 2];
                    const float x2 = acc[i][j][hrow * 2 + 1];
                    float ang = (float)(L_ + ss) * invf;
                    float cth, sth;
                    sincosf(ang, &sth, &cth);
                    float y1 = x1 * cth - x2 * sth;
                    float y2 = x2 * cth + x1 * sth;
                    size_t o = (((size_t)(bb * T_ + L_ + ss)) * HKV_ + kvh) * D_ + f;
                    kh16[o]      = h_hi(y1);
                    kh16[o + 64] = h_hi(y2);
                }
            }
        }
    } else {
        // V: plain fp16 scatter to cache layout
#pragma unroll
        for (int j = 0; j < 4; j++) {
            const int c = bn + wn + j * 8 + t4 * 2 - (H_ + HKV_ * D_);
            const int kvh = c >> 7;
            const int d = c & 127;
#pragma unroll
            for (int i = 0; i < 4; i++) {
                const int r0 = bm + wm + i * 16 + g4;
#pragma unroll
                for (int hrow = 0; hrow < 2; hrow++) {
                    const int r = r0 + hrow * 8;
                    const int bb = r >> 9;
                    const int ss = r & 511;
                    size_t o = (((size_t)(bb * T_ + L_ + ss)) * HKV_ + kvh) * D_ + d;
                    *reinterpret_cast<uint32_t*>(vh16 + o) =
                        pack_h2(acc[i][j][hrow * 2], acc[i][j][hrow * 2 + 1]);
                }
            }
        }
    }
}

// ---------------- cache -> fp16 (hi only) ------------------------------------
__global__ void copy_cache_kernel(const float4* __restrict__ kc,
                                  const float4* __restrict__ vc)
{
    int idx = blockIdx.x * blockDim.x + threadIdx.x;
    const int n = B_ * L_ * HKV_ * D_ / 4;
    if (idx >= n) return;
    const int perb4 = L_ * HKV_ * D_ / 4;
    int b = idx / perb4;
    size_t o = ((size_t)idx + (size_t)b * ((T_ - L_) * HKV_ * D_ / 4)) * 4;
    float4 k = kc[idx];
    float4 v = vc[idx];
    *reinterpret_cast<uint2*>(reinterpret_cast<uint16_t*>(g_kb_h) + o) =
        make_uint2(pack_h2(k.x, k.y), pack_h2(k.z, k.w));
    *reinterpret_cast<uint2*>(reinterpret_cast<uint16_t*>(g_vb_h) + o) =
        make_uint2(pack_h2(v.x, v.y), pack_h2(v.z, v.w));
}

// ============================================================================
// Tensor-core flash attention: QK 1-term (Qh·Kh), PV 1-term (Ph·Vh)
// ============================================================================
#define AT_STAGE 32768
#define AT_SMEM  (2 * AT_STAGE)
#define SC_LOG2E 0.12751884817f

__global__ __launch_bounds__(256, 1) void attn_mma()
{
    extern __shared__ char smem[];
    const uint32_t sb = smem_u32(smem);
    const int tid  = threadIdx.x;
    const int lane = tid & 31;
    const int w    = tid >> 5;
    const int g    = lane >> 2;
    const int t4   = lane & 3;
    const int qt   = blockIdx.x;
    const int hq   = blockIdx.y;
    const int b    = blockIdx.z;
    const int kvh  = hq >> 2;

    // stage Q hi (32KB), fragment to registers
    {
        const int qr  = tid >> 1;
        const int qcb = (tid & 1) * 8;
        const size_t qo = ((size_t)(b * S_ + qt * 128 + qr)) * (HQ_ * D_) + hq * D_;
#pragma unroll
        for (int i = 0; i < 8; i++) {
            int ch = qcb + i;
            uint32_t d = sb + qr * 256 + ((ch ^ (qr & 7)) * 16);
            CP_ASYNC16(d, g_qb_h + qo + ch * 8);
        }
        CP_COMMIT();
        CP_WAIT0();
    }
    __syncthreads();

    uint32_t qh[8][4];
    {
        const int tt  = lane >> 3;
        const int qrow = 16 * w + (tt & 1) * 8 + (lane & 7);
        const int chi  = tt >> 1;
#pragma unroll
        for (int kk = 0; kk < 8; kk++) {
            uint32_t a = sb + qrow * 256 + (((2 * kk + chi) ^ (qrow & 7)) * 16);
            LDSM4(qh[kk], a);
        }
    }
    __syncthreads();

    const int ntiles = 26 + 2 * qt;
    const int mask_from = 24 + 2 * qt;

    auto issueKV = [&](int stage, int kt) {
        const uint32_t s = sb + stage * AT_STAGE;
        const int trow = tid >> 2;
        const int cb   = (tid & 3) * 4;
        const size_t go = (((size_t)(b * T_ + kt * 64 + trow)) * HKV_ + kvh) * D_;
        const uint32_t rb = s + trow * 256;
#pragma unroll
        for (int i = 0; i < 4; i++) {
            int ch = cb + i;
            uint32_t d = rb + ((ch ^ (trow & 7)) * 16);
            CP_ASYNC16(d,         g_kb_h + go + ch * 8);
            CP_ASYNC16(d + 16384, g_vb_h + go + ch * 8);
        }
        CP_COMMIT();
    };

    issueKV(0, 0);
    issueKV(1, 1);

    float oacc[16][4];
#pragma unroll
    for (int j = 0; j < 16; j++) {
        oacc[j][0] = 0.f; oacc[j][1] = 0.f; oacc[j][2] = 0.f; oacc[j][3] = 0.f;
    }
    float m0 = -1e30f, m1 = -1e30f, l0 = 0.f, l1 = 0.f;

    const int tt   = lane >> 3;
    const int krb  = (tt >> 1) * 8 + (lane & 7);
    const int kch1 = tt & 1;
    const int vrb  = (tt & 1) * 8 + (lane & 7);
    const int vch1 = tt >> 1;

    for (int kt = 0; kt < ntiles; kt++) {
        if (kt + 1 < ntiles) { CP_WAIT1(); } else { CP_WAIT0(); }
        __syncthreads();

        const uint32_t s = sb + (kt & 1) * AT_STAGE;

        float sacc[8][4];
#pragma unroll
        for (int j = 0; j < 8; j++) {
            sacc[j][0] = 0.f; sacc[j][1] = 0.f; sacc[j][2] = 0.f; sacc[j][3] = 0.f;
        }
#pragma unroll
        for (int kk = 0; kk < 8; kk++) {
#pragma unroll
            for (int jp = 0; jp < 4; jp++) {
                const int trow = jp * 16 + krb;
                const uint32_t addr = s + trow * 256 +
                                      (((2 * kk + kch1) ^ (trow & 7)) * 16);
                uint32_t bh[4];
                LDSM4(bh, addr);
                MMA_F16(sacc[2*jp],   qh[kk], bh[0], bh[1]);
                MMA_F16(sacc[2*jp+1], qh[kk], bh[2], bh[3]);
            }
        }

        if (kt >= mask_from) {
            const int colb = kt * 64 + 2 * t4;
            const int alw0 = L_ + qt * 128 + 16 * w + g;
            const int alw1 = alw0 + 8;
#pragma unroll
            for (int j = 0; j < 8; j++) {
                int c0 = colb + j * 8;
                if (c0 > alw0)     sacc[j][0] = -1e30f;
                if (c0 + 1 > alw0) sacc[j][1] = -1e30f;
                if (c0 > alw1)     sacc[j][2] = -1e30f;
                if (c0 + 1 > alw1) sacc[j][3] = -1e30f;
            }
        }

        float rm0 = -1e30f, rm1 = -1e30f;
#pragma unroll
        for (int j = 0; j < 8; j++) {
            rm0 = fmaxf(rm0, fmaxf(sacc[j][0], sacc[j][1]));
            rm1 = fmaxf(rm1, fmaxf(sacc[j][2], sacc[j][3]));
        }
        rm0 = fmaxf(rm0, __shfl_xor_sync(0xFFFFFFFFu, rm0, 1));
        rm0 = fmaxf(rm0, __shfl_xor_sync(0xFFFFFFFFu, rm0, 2));
        rm1 = fmaxf(rm1, __shfl_xor_sync(0xFFFFFFFFu, rm1, 1));
        rm1 = fmaxf(rm1, __shfl_xor_sync(0xFFFFFFFFu, rm1, 2));

        const float nm0 = fmaxf(m0, rm0), nm1 = fmaxf(m1, rm1);
        const float f0 = exp2f((m0 - nm0) * SC_LOG2E);
        const float f1 = exp2f((m1 - nm1) * SC_LOG2E);
        float rs0 = 0.f, rs1 = 0.f;
#pragma unroll
        for (int j = 0; j < 8; j++) {
            sacc[j][0] = exp2f((sacc[j][0] - nm0) * SC_LOG2E);
            sacc[j][1] = exp2f((sacc[j][1] - nm0) * SC_LOG2E);
            sacc[j][2] = exp2f((sacc[j][2] - nm1) * SC_LOG2E);
            sacc[j][3] = exp2f((sacc[j][3] - nm1) * SC_LOG2E);
            rs0 += sacc[j][0] + sacc[j][1];
            rs1 += sacc[j][2] + sacc[j][3];
        }
        rs0 += __shfl_xor_sync(0xFFFFFFFFu, rs0, 1);
        rs0 += __shfl_xor_sync(0xFFFFFFFFu, rs0, 2);
        rs1 += __shfl_xor_sync(0xFFFFFFFFu, rs1, 1);
        rs1 += __shfl_xor_sync(0xFFFFFFFFu, rs1, 2);
        l0 = l0 * f0 + rs0;
        l1 = l1 * f1 + rs1;
        m0 = nm0; m1 = nm1;

#pragma unroll
        for (int j = 0; j < 16; j++) {
            oacc[j][0] *= f0; oacc[j][1] *= f0;
            oacc[j][2] *= f1; oacc[j][3] *= f1;
        }

        uint32_t ph[4][4];
#pragma unroll
        for (int kc = 0; kc < 4; kc++) {
            ph[kc][0] = pack_h2(sacc[2*kc][0],   sacc[2*kc][1]);
            ph[kc][1] = pack_h2(sacc[2*kc][2],   sacc[2*kc][3]);
            ph[kc][2] = pack_h2(sacc[2*kc+1][0], sacc[2*kc+1][1]);
            ph[kc][3] = pack_h2(sacc[2*kc+1][2], sacc[2*kc+1][3]);
        }

        const uint32_t vbase = s + 16384;
#pragma unroll
        for (int jp2 = 0; jp2 < 8; jp2++) {
#pragma unroll
            for (int kc = 0; kc < 4; kc++) {
                const int trow = kc * 16 + vrb;
                const uint32_t addr = vbase + trow * 256 +
                                      (((jp2 * 2 + vch1) ^ (trow & 7)) * 16);
                uint32_t vh[4];
                LDSM4T(vh, addr);
                MMA_F16(oacc[2*jp2],   ph[kc], vh[0], vh[1]);
                MMA_F16(oacc[2*jp2+1], ph[kc], vh[2], vh[3]);
            }
        }

        __syncthreads();
        if (kt + 2 < ntiles) issueKV(kt & 1, kt + 2);
    }

    const float il0 = 1.0f / l0;
    const float il1 = 1.0f / l1;
    const size_t tok0 = (size_t)(b * S_ + qt * 128 + 16 * w + g);
    uint32_t* oh32 = reinterpret_cast<uint32_t*>(g_attb_h);
#pragma unroll
    for (int jn = 0; jn < 16; jn++) {
        float o0 = oacc[jn][0] * il0, o1 = oacc[jn][1] * il0;
        float o2 = oacc[jn][2] * il1, o3 = oacc[jn][3] * il1;
        const size_t a0 = (tok0 * (HQ_ * D_) + hq * D_ + jn * 8 + 2 * t4) >> 1;
        const size_t a1 = a0 + (8 * (HQ_ * D_) >> 1);
        oh32[a0] = pack_h2(o0, o1);
        oh32[a1] = pack_h2(o2, o3);
    }
}

// ---------------- launcher ---------------------------------------------------
extern "C" void kernel_launch(void* const* d_in, const int* in_sizes, int n_in,
                              void* d_out, int out_size)
{
    const float* hidden  = (const float*)d_in[0];
    const float* k_cache = (const float*)d_in[1];
    const float* v_cache = (const float*)d_in[2];
    const float* wq      = (const float*)d_in[3];
    const float* wk      = (const float*)d_in[4];
    const float* wv      = (const float*)d_in[5];
    const float* wo      = (const float*)d_in[6];
    float* out = (float*)d_out;

    __half *hid_h, *wqkv_h, *wo_h, *attb_h;
    cudaGetSymbolAddress((void**)&hid_h,  g_hid_h);
    cudaGetSymbolAddress((void**)&wqkv_h, g_wqkvT_h);
    cudaGetSymbolAddress((void**)&wo_h,   g_woT_h);
    cudaGetSymbolAddress((void**)&attb_h, g_attb_h);

    cudaFuncSetAttribute(gemm_h1,
                         cudaFuncAttributeMaxDynamicSharedMemorySize, GEMM_SMEM);
    cudaFuncSetAttribute(attn_mma,
                         cudaFuncAttributeMaxDynamicSharedMemorySize, AT_SMEM);

    // conversions (Q/K weight sections permuted for fused-RoPE epilogue)
    conv_h<<<(NT_ * H_ / 4 + 255) / 256, 256>>>(
        (const float4*)hidden, (uint2*)hid_h, NT_ * H_ / 4);
    conv_hT<<<dim3(H_ / 32, H_ / 64), 256>>>(wq, wqkv_h, H_, H_, 1);
    conv_hT<<<dim3((HKV_ * D_) / 32, H_ / 64), 256>>>(
        wk, wqkv_h + (size_t)H_ * H_, H_, HKV_ * D_, 1);
    conv_hT<<<dim3((HKV_ * D_) / 32, H_ / 64), 256>>>(
        wv, wqkv_h + (size_t)(H_ + HKV_ * D_) * H_, H_, HKV_ * D_, 0);
    conv_hT<<<dim3(H_ / 32, H_ / 64), 256>>>(wo, wo_h, H_, H_, 0);

    // cache -> fp16
    copy_cache_kernel<<<(B_ * L_ * HKV_ * D_ / 4) / 256, 256>>>(
        (const float4*)k_cache, (const float4*)v_cache);

    // fused QKV projection + RoPE + fp16 scatter
    gemm_h1<<<dim3(NQKV / 128, NT_ / 128), 256, GEMM_SMEM>>>(
        hid_h, wqkv_h, out, H_, H_, 1);

    // attention
    attn_mma<<<dim3(S_ / 128, HQ_, B_), 256, AT_SMEM>>>();

    // output projection
    gemm_h1<<<dim3(H_ / 128, NT_ / 128), 256, GEMM_SMEM>>>(
        attb_h, wo_h, out, H_, H_, 0);
}

// round 14
// speedup vs baseline: 1.1655x; 1.0690x over previous
#include <cuda_runtime.h>
#include <cuda_fp16.h>
#include <math.h>
#include <stdint.h>

// Problem constants
#define B_    8
#define S_    512
#define H_    4096
#define HQ_   32
#define HKV_  8
#define D_    128
#define L_    1536
#define T_    2048
#define NT_   (B_*S_)
#define THETA_ 500000.0f
#define NQKV  (H_ + 2*HKV_*D_)      // 6144
// -log2(THETA)/64
#define ROPE_C (-0.2958058953f)

// ---------------- scratch (device globals) ----------------------------------
__device__ __half g_hid_h [(size_t)NT_*H_];
__device__ __half g_wqkvT_h[(size_t)NQKV*H_];
__device__ __half g_woT_h [(size_t)H_*H_];
__device__ __half g_attb_h[(size_t)NT_*H_];

__device__ __half g_qb_h[(size_t)NT_*HQ_*D_];
__device__ __half g_kb_h[(size_t)B_*T_*HKV_*D_];
__device__ __half g_vb_h[(size_t)B_*T_*HKV_*D_];

// ---------------- helpers ----------------------------------------------------
__device__ __forceinline__ uint32_t smem_u32(const void* p) {
    uint32_t r;
    asm("{ .reg .u64 t; cvta.to.shared.u64 t, %1; cvt.u32.u64 %0, t; }"
        : "=r"(r) : "l"(p));
    return r;
}
__device__ __forceinline__ uint16_t h_hi(float x) {
    __half h = __float2half_rn(x);
    return *reinterpret_cast<uint16_t*>(&h);
}
__device__ __forceinline__ uint32_t pack_h2(float lo, float hi) {
    __half2 h = __floats2half2_rn(lo, hi);       // lo -> low half
    return *reinterpret_cast<uint32_t*>(&h);
}

#define CP_ASYNC16(dst, src) \
    asm volatile("cp.async.cg.shared.global [%0], [%1], 16;" :: "r"(dst), "l"(src))
#define CP_COMMIT() asm volatile("cp.async.commit_group;")
#define CP_WAIT2()  asm volatile("cp.async.wait_group 2;")
#define CP_WAIT1()  asm volatile("cp.async.wait_group 1;")
#define CP_WAIT0()  asm volatile("cp.async.wait_group 0;")

#define LDSM4(r, a) \
    asm volatile("ldmatrix.sync.aligned.m8n8.x4.shared.b16 {%0,%1,%2,%3}, [%4];" \
                 : "=r"((r)[0]), "=r"((r)[1]), "=r"((r)[2]), "=r"((r)[3]) : "r"(a))
#define LDSM4T(r, a) \
    asm volatile("ldmatrix.sync.aligned.m8n8.x4.trans.shared.b16 {%0,%1,%2,%3}, [%4];" \
                 : "=r"((r)[0]), "=r"((r)[1]), "=r"((r)[2]), "=r"((r)[3]) : "r"(a))

#define MMA_F16(c, a, b0v, b1v) \
    asm volatile("mma.sync.aligned.m16n8k16.row.col.f32.f16.f16.f32 " \
                 "{%0,%1,%2,%3}, {%4,%5,%6,%7}, {%8,%9}, {%0,%1,%2,%3};" \
                 : "+f"((c)[0]), "+f"((c)[1]), "+f"((c)[2]), "+f"((c)[3]) \
                 : "r"((a)[0]), "r"((a)[1]), "r"((a)[2]), "r"((a)[3]), \
                   "r"(b0v), "r"(b1v))

// ---------------- fp32 -> fp16 (hi only) -------------------------------------
__global__ void conv_h(const float4* __restrict__ in, uint2* __restrict__ oh, int n4)
{
    int i = blockIdx.x * blockDim.x + threadIdx.x;
    if (i >= n4) return;
    float4 v = in[i];
    oh[i] = make_uint2(pack_h2(v.x, v.y), pack_h2(v.z, v.w));
}

// ---------------- merged QKV weight transpose -> fp16 [NQKV][4096] -----------
// Q rows [0,4096) from wq (perm), K rows [4096,5120) from wk (perm),
// V rows [5120,6144) from wv (no perm). perm: d -> (d<64 ? 2d : 2(d-64)+1).
__global__ void conv_hT_qkv(const float* __restrict__ wq,
                            const float* __restrict__ wk,
                            const float* __restrict__ wv,
                            __half* __restrict__ oh)
{
    __shared__ float t[64][33];
    const int n0 = blockIdx.x * 32;
    const int k0 = blockIdx.y * 64;
    const float* in;
    int N, nloc, perm;
    if (n0 < H_) {
        in = wq; N = H_; nloc = n0; perm = 1;
    } else if (n0 < H_ + HKV_ * D_) {
        in = wk; N = HKV_ * D_; nloc = n0 - H_; perm = 1;
    } else {
        in = wv; N = HKV_ * D_; nloc = n0 - H_ - HKV_ * D_; perm = 0;
    }
    const int x = threadIdx.x & 31;
    const int y = threadIdx.x >> 5;
#pragma unroll
    for (int it = 0; it < 8; it++) {
        int row = it * 8 + y;
        t[row][x] = in[(size_t)(k0 + row) * N + nloc + x];
    }
    __syncthreads();
    const int u  = threadIdx.x & 31;
    const int nr = threadIdx.x >> 5;
    uint16_t* o16 = reinterpret_cast<uint16_t*>(oh);
#pragma unroll
    for (int it = 0; it < 4; it++) {
        int n = it * 8 + nr;
        int gn = n0 + n;
        int dst = gn;
        if (perm) {
            int d = gn & 127;
            int pd = (d < 64) ? (2 * d) : (2 * (d - 64) + 1);
            dst = (gn & ~127) | pd;
        }
        uint32_t p = pack_h2(t[2 * u][n], t[2 * u + 1][n]);
        *reinterpret_cast<uint32_t*>(o16 + (size_t)dst * H_ + k0 + 2 * u) = p;
    }
}

// ---------------- wo transpose -> fp16 [4096][4096] --------------------------
__global__ void conv_hT(const float* __restrict__ in,
                        __half* __restrict__ oh, int K, int N)
{
    __shared__ float t[64][33];
    const int n0 = blockIdx.x * 32;
    const int k0 = blockIdx.y * 64;
    const int x = threadIdx.x & 31;
    const int y = threadIdx.x >> 5;
#pragma unroll
    for (int it = 0; it < 8; it++) {
        int row = it * 8 + y;
        t[row][x] = in[(size_t)(k0 + row) * N + n0 + x];
    }
    __syncthreads();
    const int u  = threadIdx.x & 31;
    const int nr = threadIdx.x >> 5;
    uint16_t* o16 = reinterpret_cast<uint16_t*>(oh);
#pragma unroll
    for (int it = 0; it < 4; it++) {
        int n = it * 8 + nr;
        uint32_t p = pack_h2(t[2 * u][n], t[2 * u + 1][n]);
        *reinterpret_cast<uint32_t*>(o16 + (size_t)(n0 + n) * K + k0 + 2 * u) = p;
    }
}

// ============================================================================
// fp16 1-term GEMM, BK=64 (half the barriers of BK=32).
// smem/stage: A 16K | B 16K = 32KB; 3 stages = 96KB.
// Row layout: 128B/row (8 chunks of 16B), swizzle chunk' = chunk ^ (row & 7).
// mode 0: fp32 out; mode 1: fused QKV epilogue (RoPE + fp16 scatter).
// ============================================================================
#define GSTAGE 32768
#define GEMM_SMEM (3 * GSTAGE)

__global__ __launch_bounds__(256) void gemm_h1(
    const __half* __restrict__ Ah, const __half* __restrict__ Bh,
    float* __restrict__ C0, int ld0, int K, int mode)
{
    extern __shared__ char smem[];
    const uint32_t sb = smem_u32(smem);
    const int tid  = threadIdx.x;
    const int lane = tid & 31;
    const int wid  = tid >> 5;
    const int bm   = blockIdx.y * 128;
    const int bn   = blockIdx.x * 128;
    const int wm   = (wid >> 2) * 64;
    const int wn   = (wid & 3) * 32;

    // loader: 32 rows x 8 chunks per pass, 4 passes per operand
    const int lrow8 = tid >> 3;      // 0..31
    const int lchk8 = tid & 7;       // 0..7

    // fragment addressing (XOR key = lane & 7 for both operands)
    const int xk    = lane & 7;
    const int arow  = ((lane >> 3) & 1) * 8 + (lane & 7);
    const int akc   = lane >> 4;
    const uint32_t aBase = (uint32_t)((wm + arow) * 128);
    const int brow8 = lane & 7;
    const int bkc   = (lane >> 3) & 1;
    const int bj1   = (lane >> 4) & 1;
    const uint32_t bBase = (uint32_t)((wn + bj1 * 8 + brow8) * 128);

    float acc[4][4][4];
#pragma unroll
    for (int i = 0; i < 4; i++)
#pragma unroll
        for (int j = 0; j < 4; j++) {
            acc[i][j][0] = 0.f; acc[i][j][1] = 0.f;
            acc[i][j][2] = 0.f; acc[i][j][3] = 0.f;
        }

    const int nk = K / 64;   // 64 chunks

    auto issue = [&](int st, int k0) {
        const uint32_t s = sb + st * GSTAGE;
#pragma unroll
        for (int p = 0; p < 4; p++) {
            const int row = lrow8 + p * 32;
            const uint32_t sw = (uint32_t)(row * 128 + ((lchk8 ^ (row & 7)) * 16));
            CP_ASYNC16(s + sw, Ah + (size_t)(bm + row) * K + k0 + lchk8 * 8);
            CP_ASYNC16(s + 16384 + sw, Bh + (size_t)(bn + row) * K + k0 + lchk8 * 8);
        }
        CP_COMMIT();
    };

    issue(0, 0);
    issue(1, 64);
    issue(2, 128);

    int st = 0;
    for (int ck = 0; ck < nk; ck++) {
        const int rem = nk - 1 - ck;
        if (rem >= 2) { CP_WAIT2(); } else if (rem == 1) { CP_WAIT1(); } else { CP_WAIT0(); }
        __syncthreads();

        const uint32_t sA  = sb + st * GSTAGE + aBase;
        const uint32_t sBH = sb + st * GSTAGE + 16384 + bBase;

#pragma unroll
        for (int ks = 0; ks < 4; ks++) {
            const uint32_t cA = (uint32_t)(((ks * 2 + akc) ^ xk) * 16);
            const uint32_t cB = (uint32_t)(((ks * 2 + bkc) ^ xk) * 16);

            uint32_t aF[4][4];
#pragma unroll
            for (int i = 0; i < 4; i++) LDSM4(aF[i], sA + i * 2048 + cA);

            uint32_t bH[4][2];
#pragma unroll
            for (int jp = 0; jp < 2; jp++) {
                uint32_t r4[4];
                LDSM4(r4, sBH + jp * 2048 + cB);
                bH[2*jp][0] = r4[0]; bH[2*jp][1] = r4[1];
                bH[2*jp+1][0] = r4[2]; bH[2*jp+1][1] = r4[3];
            }

#pragma unroll
            for (int i = 0; i < 4; i++)
#pragma unroll
                for (int j = 0; j < 4; j++)
                    MMA_F16(acc[i][j], aF[i], bH[j][0], bH[j][1]);
        }
        __syncthreads();
        if (ck + 3 < nk) issue(st, (ck + 3) * 64);
        st = (st == 2) ? 0 : st + 1;
    }

    const int g4 = lane >> 2, t4 = lane & 3;

    if (mode == 0) {
#pragma unroll
        for (int i = 0; i < 4; i++) {
            const int row = bm + wm + i * 16 + g4;
#pragma unroll
            for (int j = 0; j < 4; j++) {
                const int col = bn + wn + j * 8 + t4 * 2;
                *reinterpret_cast<float2*>(&C0[(size_t)row * ld0 + col]) =
                    make_float2(acc[i][j][0], acc[i][j][1]);
                *reinterpret_cast<float2*>(&C0[(size_t)(row + 8) * ld0 + col]) =
                    make_float2(acc[i][j][2], acc[i][j][3]);
            }
        }
        return;
    }

    // ---- fused QKV epilogue ----
    uint16_t* qh16 = reinterpret_cast<uint16_t*>(g_qb_h);
    uint16_t* kh16 = reinterpret_cast<uint16_t*>(g_kb_h);
    uint16_t* vh16 = reinterpret_cast<uint16_t*>(g_vb_h);

    if (bn < H_) {
        // Q: RoPE pair in adjacent cols (hi only)
#pragma unroll
        for (int j = 0; j < 4; j++) {
            const int c = bn + wn + j * 8 + t4 * 2;
            const int head = c >> 7;
            const int f = (c & 127) >> 1;
            const float invf = exp2f((float)f * ROPE_C);
#pragma unroll
            for (int i = 0; i < 4; i++) {
                const int r0 = bm + wm + i * 16 + g4;
#pragma unroll
                for (int hrow = 0; hrow < 2; hrow++) {
                    const int r = r0 + hrow * 8;
                    const float x1 = acc[i][j][hrow * 2];
                    const float x2 = acc[i][j][hrow * 2 + 1];
                    float ang = (float)(L_ + (r & 511)) * invf;
                    float cth, sth;
                    sincosf(ang, &sth, &cth);
                    float y1 = x1 * cth - x2 * sth;
                    float y2 = x2 * cth + x1 * sth;
                    size_t base = (size_t)r * (HQ_ * D_) + head * D_ + f;
                    qh16[base]      = h_hi(y1);
                    qh16[base + 64] = h_hi(y2);
                }
            }
        }
    } else if (bn < H_ + HKV_ * D_) {
        // K: RoPE + scatter to cache layout (hi only)
#pragma unroll
        for (int j = 0; j < 4; j++) {
            const int c = bn + wn + j * 8 + t4 * 2 - H_;
            const int kvh = c >> 7;
            const int f = (c & 127) >> 1;
            const float invf = exp2f((float)f * ROPE_C);
#pragma unroll
            for (int i = 0; i < 4; i++) {
                const int r0 = bm + wm + i * 16 + g4;
#pragma unroll
                for (int hrow = 0; hrow < 2; hrow++) {
                    const int r = r0 + hrow * 8;
                    const int bb = r >> 9;
                    const int ss = r & 511;
                    const float x1 = acc[i][j][hrow * 2];
                    const float x2 = acc[i][j][hrow * 2 + 1];
                    float ang = (float)(L_ + ss) * invf;
                    float cth, sth;
                    sincosf(ang, &sth, &cth);
                    float y1 = x1 * cth - x2 * sth;
                    float y2 = x2 * cth + x1 * sth;
                    size_t o = (((size_t)(bb * T_ + L_ + ss)) * HKV_ + kvh) * D_ + f;
                    kh16[o]      = h_hi(y1);
                    kh16[o + 64] = h_hi(y2);
                }
            }
        }
    } else {
        // V: plain fp16 scatter to cache layout
#pragma unroll
        for (int j = 0; j < 4; j++) {
            const int c = bn + wn + j * 8 + t4 * 2 - (H_ + HKV_ * D_);
            const int kvh = c >> 7;
            const int d = c & 127;
#pragma unroll
            for (int i = 0; i < 4; i++) {
                const int r0 = bm + wm + i * 16 + g4;
#pragma unroll
                for (int hrow = 0; hrow < 2; hrow++) {
                    const int r = r0 + hrow * 8;
                    const int bb = r >> 9;
                    const int ss = r & 511;
                    size_t o = (((size_t)(bb * T_ + L_ + ss)) * HKV_ + kvh) * D_ + d;
                    *reinterpret_cast<uint32_t*>(vh16 + o) =
                        pack_h2(acc[i][j][hrow * 2], acc[i][j][hrow * 2 + 1]);
                }
            }
        }
    }
}

// ---------------- cache -> fp16 (hi only) ------------------------------------
__global__ void copy_cache_kernel(const float4* __restrict__ kc,
                                  const float4* __restrict__ vc)
{
    int idx = blockIdx.x * blockDim.x + threadIdx.x;
    const int n = B_ * L_ * HKV_ * D_ / 4;
    if (idx >= n) return;
    const int perb4 = L_ * HKV_ * D_ / 4;
    int b = idx / perb4;
    size_t o = ((size_t)idx + (size_t)b * ((T_ - L_) * HKV_ * D_ / 4)) * 4;
    float4 k = kc[idx];
    float4 v = vc[idx];
    *reinterpret_cast<uint2*>(reinterpret_cast<uint16_t*>(g_kb_h) + o) =
        make_uint2(pack_h2(k.x, k.y), pack_h2(k.z, k.w));
    *reinterpret_cast<uint2*>(reinterpret_cast<uint16_t*>(g_vb_h) + o) =
        make_uint2(pack_h2(v.x, v.y), pack_h2(v.z, v.w));
}

// ============================================================================
// Tensor-core flash attention: QK 1-term, PV 1-term; longest q-tiles first
// ============================================================================
#define AT_STAGE 32768
#define AT_SMEM  (2 * AT_STAGE)
#define SC_LOG2E 0.12751884817f

__global__ __launch_bounds__(256, 1) void attn_mma()
{
    extern __shared__ char smem[];
    const uint32_t sb = smem_u32(smem);
    const int tid  = threadIdx.x;
    const int lane = tid & 31;
    const int w    = tid >> 5;
    const int g    = lane >> 2;
    const int t4   = lane & 3;
    const int qt   = (S_ / 128 - 1) - blockIdx.x;   // longest tiles first
    const int hq   = blockIdx.y;
    const int b    = blockIdx.z;
    const int kvh  = hq >> 2;

    // stage Q hi (32KB), fragment to registers
    {
        const int qr  = tid >> 1;
        const int qcb = (tid & 1) * 8;
        const size_t qo = ((size_t)(b * S_ + qt * 128 + qr)) * (HQ_ * D_) + hq * D_;
#pragma unroll
        for (int i = 0; i < 8; i++) {
            int ch = qcb + i;
            uint32_t d = sb + qr * 256 + ((ch ^ (qr & 7)) * 16);
            CP_ASYNC16(d, g_qb_h + qo + ch * 8);
        }
        CP_COMMIT();
        CP_WAIT0();
    }
    __syncthreads();

    uint32_t qh[8][4];
    {
        const int tt  = lane >> 3;
        const int qrow = 16 * w + (tt & 1) * 8 + (lane & 7);
        const int chi  = tt >> 1;
#pragma unroll
        for (int kk = 0; kk < 8; kk++) {
            uint32_t a = sb + qrow * 256 + (((2 * kk + chi) ^ (qrow & 7)) * 16);
            LDSM4(qh[kk], a);
        }
    }
    __syncthreads();

    const int ntiles = 26 + 2 * qt;
    const int mask_from = 24 + 2 * qt;

    auto issueKV = [&](int stage, int kt) {
        const uint32_t s = sb + stage * AT_STAGE;
        const int trow = tid >> 2;
        const int cb   = (tid & 3) * 4;
        const size_t go = (((size_t)(b * T_ + kt * 64 + trow)) * HKV_ + kvh) * D_;
        const uint32_t rb = s + trow * 256;
#pragma unroll
        for (int i = 0; i < 4; i++) {
            int ch = cb + i;
            uint32_t d = rb + ((ch ^ (trow & 7)) * 16);
            CP_ASYNC16(d,         g_kb_h + go + ch * 8);
            CP_ASYNC16(d + 16384, g_vb_h + go + ch * 8);
        }
        CP_COMMIT();
    };

    issueKV(0, 0);
    issueKV(1, 1);

    float oacc[16][4];
#pragma unroll
    for (int j = 0; j < 16; j++) {
        oacc[j][0] = 0.f; oacc[j][1] = 0.f; oacc[j][2] = 0.f; oacc[j][3] = 0.f;
    }
    float m0 = -1e30f, m1 = -1e30f, l0 = 0.f, l1 = 0.f;

    const int tt   = lane >> 3;
    const int krb  = (tt >> 1) * 8 + (lane & 7);
    const int kch1 = tt & 1;
    const int vrb  = (tt & 1) * 8 + (lane & 7);
    const int vch1 = tt >> 1;

    for (int kt = 0; kt < ntiles; kt++) {
        if (kt + 1 < ntiles) { CP_WAIT1(); } else { CP_WAIT0(); }
        __syncthreads();

        const uint32_t s = sb + (kt & 1) * AT_STAGE;

        float sacc[8][4];
#pragma unroll
        for (int j = 0; j < 8; j++) {
            sacc[j][0] = 0.f; sacc[j][1] = 0.f; sacc[j][2] = 0.f; sacc[j][3] = 0.f;
        }
#pragma unroll
        for (int kk = 0; kk < 8; kk++) {
#pragma unroll
            for (int jp = 0; jp < 4; jp++) {
                const int trow = jp * 16 + krb;
                const uint32_t addr = s + trow * 256 +
                                      (((2 * kk + kch1) ^ (trow & 7)) * 16);
                uint32_t bh[4];
                LDSM4(bh, addr);
                MMA_F16(sacc[2*jp],   qh[kk], bh[0], bh[1]);
                MMA_F16(sacc[2*jp+1], qh[kk], bh[2], bh[3]);
            }
        }

        if (kt >= mask_from) {
            const int colb = kt * 64 + 2 * t4;
            const int alw0 = L_ + qt * 128 + 16 * w + g;
            const int alw1 = alw0 + 8;
#pragma unroll
            for (int j = 0; j < 8; j++) {
                int c0 = colb + j * 8;
                if (c0 > alw0)     sacc[j][0] = -1e30f;
                if (c0 + 1 > alw0) sacc[j][1] = -1e30f;
                if (c0 > alw1)     sacc[j][2] = -1e30f;
                if (c0 + 1 > alw1) sacc[j][3] = -1e30f;
            }
        }

        float rm0 = -1e30f, rm1 = -1e30f;
#pragma unroll
        for (int j = 0; j < 8; j++) {
            rm0 = fmaxf(rm0, fmaxf(sacc[j][0], sacc[j][1]));
            rm1 = fmaxf(rm1, fmaxf(sacc[j][2], sacc[j][3]));
        }
        rm0 = fmaxf(rm0, __shfl_xor_sync(0xFFFFFFFFu, rm0, 1));
        rm0 = fmaxf(rm0, __shfl_xor_sync(0xFFFFFFFFu, rm0, 2));
        rm1 = fmaxf(rm1, __shfl_xor_sync(0xFFFFFFFFu, rm1, 1));
        rm1 = fmaxf(rm1, __shfl_xor_sync(0xFFFFFFFFu, rm1, 2));

        const float nm0 = fmaxf(m0, rm0), nm1 = fmaxf(m1, rm1);
        const float f0 = exp2f((m0 - nm0) * SC_LOG2E);
        const float f1 = exp2f((m1 - nm1) * SC_LOG2E);
        float rs0 = 0.f, rs1 = 0.f;
#pragma unroll
        for (int j = 0; j < 8; j++) {
            sacc[j][0] = exp2f((sacc[j][0] - nm0) * SC_LOG2E);
            sacc[j][1] = exp2f((sacc[j][1] - nm0) * SC_LOG2E);
            sacc[j][2] = exp2f((sacc[j][2] - nm1) * SC_LOG2E);
            sacc[j][3] = exp2f((sacc[j][3] - nm1) * SC_LOG2E);
            rs0 += sacc[j][0] + sacc[j][1];
            rs1 += sacc[j][2] + sacc[j][3];
        }
        rs0 += __shfl_xor_sync(0xFFFFFFFFu, rs0, 1);
        rs0 += __shfl_xor_sync(0xFFFFFFFFu, rs0, 2);
        rs1 += __shfl_xor_sync(0xFFFFFFFFu, rs1, 1);
        rs1 += __shfl_xor_sync(0xFFFFFFFFu, rs1, 2);
        l0 = l0 * f0 + rs0;
        l1 = l1 * f1 + rs1;
        m0 = nm0; m1 = nm1;

#pragma unroll
        for (int j = 0; j < 16; j++) {
            oacc[j][0] *= f0; oacc[j][1] *= f0;
            oacc[j][2] *= f1; oacc[j][3] *= f1;
        }

        uint32_t ph[4][4];
#pragma unroll
        for (int kc = 0; kc < 4; kc++) {
            ph[kc][0] = pack_h2(sacc[2*kc][0],   sacc[2*kc][1]);
            ph[kc][1] = pack_h2(sacc[2*kc][2],   sacc[2*kc][3]);
            ph[kc][2] = pack_h2(sacc[2*kc+1][0], sacc[2*kc+1][1]);
            ph[kc][3] = pack_h2(sacc[2*kc+1][2], sacc[2*kc+1][3]);
        }

        const uint32_t vbase = s + 16384;
#pragma unroll
        for (int jp2 = 0; jp2 < 8; jp2++) {
#pragma unroll
            for (int kc = 0; kc < 4; kc++) {
                const int trow = kc * 16 + vrb;
                const uint32_t addr = vbase + trow * 256 +
                                      (((jp2 * 2 + vch1) ^ (trow & 7)) * 16);
                uint32_t vh[4];
                LDSM4T(vh, addr);
                MMA_F16(oacc[2*jp2],   ph[kc], vh[0], vh[1]);
                MMA_F16(oacc[2*jp2+1], ph[kc], vh[2], vh[3]);
            }
        }

        __syncthreads();
        if (kt + 2 < ntiles) issueKV(kt & 1, kt + 2);
    }

    const float il0 = 1.0f / l0;
    const float il1 = 1.0f / l1;
    const size_t tok0 = (size_t)(b * S_ + qt * 128 + 16 * w + g);
    uint32_t* oh32 = reinterpret_cast<uint32_t*>(g_attb_h);
#pragma unroll
    for (int jn = 0; jn < 16; jn++) {
        float o0 = oacc[jn][0] * il0, o1 = oacc[jn][1] * il0;
        float o2 = oacc[jn][2] * il1, o3 = oacc[jn][3] * il1;
        const size_t a0 = (tok0 * (HQ_ * D_) + hq * D_ + jn * 8 + 2 * t4) >> 1;
        const size_t a1 = a0 + (8 * (HQ_ * D_) >> 1);
        oh32[a0] = pack_h2(o0, o1);
        oh32[a1] = pack_h2(o2, o3);
    }
}

// ---------------- launcher ---------------------------------------------------
extern "C" void kernel_launch(void* const* d_in, const int* in_sizes, int n_in,
                              void* d_out, int out_size)
{
    const float* hidden  = (const float*)d_in[0];
    const float* k_cache = (const float*)d_in[1];
    const float* v_cache = (const float*)d_in[2];
    const float* wq      = (const float*)d_in[3];
    const float* wk      = (const float*)d_in[4];
    const float* wv      = (const float*)d_in[5];
    const float* wo      = (const float*)d_in[6];
    float* out = (float*)d_out;

    __half *hid_h, *wqkv_h, *wo_h, *attb_h;
    cudaGetSymbolAddress((void**)&hid_h,  g_hid_h);
    cudaGetSymbolAddress((void**)&wqkv_h, g_wqkvT_h);
    cudaGetSymbolAddress((void**)&wo_h,   g_woT_h);
    cudaGetSymbolAddress((void**)&attb_h, g_attb_h);

    cudaFuncSetAttribute(gemm_h1,
                         cudaFuncAttributeMaxDynamicSharedMemorySize, GEMM_SMEM);
    cudaFuncSetAttribute(attn_mma,
                         cudaFuncAttributeMaxDynamicSharedMemorySize, AT_SMEM);

    // conversions
    conv_h<<<(NT_ * H_ / 4 + 255) / 256, 256>>>(
        (const float4*)hidden, (uint2*)hid_h, NT_ * H_ / 4);
    conv_hT_qkv<<<dim3(NQKV / 32, H_ / 64), 256>>>(wq, wk, wv, wqkv_h);
    conv_hT<<<dim3(H_ / 32, H_ / 64), 256>>>(wo, wo_h, H_, H_);

    // cache -> fp16
    copy_cache_kernel<<<(B_ * L_ * HKV_ * D_ / 4) / 256, 256>>>(
        (const float4*)k_cache, (const float4*)v_cache);

    // fused QKV projection + RoPE + fp16 scatter
    gemm_h1<<<dim3(NQKV / 128, NT_ / 128), 256, GEMM_SMEM>>>(
        hid_h, wqkv_h, out, H_, H_, 1);

    // attention
    attn_mma<<<dim3(S_ / 128, HQ_, B_), 256, AT_SMEM>>>();

    // output projection
    gemm_h1<<<dim3(H_ / 128, NT_ / 128), 256, GEMM_SMEM>>>(
        attb_h, wo_h, out, H_, H_, 0);
}